// round 1
// baseline (speedup 1.0000x reference)
#include <cuda_runtime.h>

#define NPTS  4096
#define NPQ   1024
#define NSAMP 32
#define NB    8
#define PXT   262144          /* NB*NPQ*NSAMP */
#define CF    64
#define C0    67
#define M0    64
#define M1    128
#define M2    256
#define EPSB  1e-5f
#define OUT_XYZ 24576         /* NB*NPQ*3 */

/* scratch activations (bss, no runtime alloc) */
__device__ float g_y0[(size_t)M0 * PXT];   /* 64 MB  */
__device__ float g_y1[(size_t)M1 * PXT];   /* 128 MB */

/* per-channel stats, packed: layer0 @0 (64), layer1 @64 (128), layer2 @192 (256) */
__device__ float g_sum[448];
__device__ float g_sq[448];
__device__ float g_aa[448];
__device__ float g_cc[448];

extern __shared__ float sm[];

__global__ void k_zero() {
    int t = blockIdx.x * blockDim.x + threadIdx.x;
    if (t < 448) { g_sum[t] = 0.f; g_sq[t] = 0.f; }
}

__global__ void k_fold(const float* __restrict__ gamma,
                       const float* __restrict__ beta, int off, int C) {
    int i = blockIdx.x * blockDim.x + threadIdx.x;
    if (i < C) {
        const float inv = 1.0f / (float)PXT;
        float mu  = g_sum[off + i] * inv;
        float var = g_sq[off + i] * inv - mu * mu;
        float r   = rsqrtf(var + EPSB);
        float a   = gamma[i] * r;
        g_aa[off + i] = a;
        g_cc[off + i] = beta[i] - a * mu;
    }
}

/* -------- layer 0: gather + GEMM(64 x PX x 67) + stats0 -------- */
__global__ __launch_bounds__(256) void k_gemm0(
    const float* __restrict__ xyz, const float* __restrict__ pts,
    const int* __restrict__ smp, const int* __restrict__ nbr,
    const float* __restrict__ W)
{
    float* Ws = sm;                       /* [k][co]  C0*M0  */
    float* Xs = sm + C0 * M0;             /* [k][px]  C0*128 */
    int*   s_nidx = (int*)(sm + C0 * M0 + C0 * 128);

    int tid = threadIdx.x;
    int px0 = blockIdx.x * 128;
    int b   = px0 >> 15;                  /* 128-px tile never crosses a batch */

    /* W transpose load: co fastest -> conflict-free STS, W cached in L2 */
    for (int e = tid; e < M0 * C0; e += 256) {
        int co = e & 63, k = e >> 6;
        Ws[k * M0 + co] = W[co * C0 + k];
    }
    if (tid < 128) {
        int pxg = px0 + tid;
        int ni  = nbr[pxg];
        s_nidx[tid] = ni;
        int si  = smp[pxg >> 5];
        const float* xn = xyz + (size_t)(b * NPTS + ni) * 3;
        const float* xc = xyz + (size_t)(b * NPTS + si) * 3;
        Xs[0 * 128 + tid] = xn[0] - xc[0];
        Xs[1 * 128 + tid] = xn[1] - xc[1];
        Xs[2 * 128 + tid] = xn[2] - xc[2];
    }
    __syncthreads();
    for (int e = tid; e < CF * 128; e += 256) {
        int k = e >> 7, px = e & 127;
        Xs[(3 + k) * 128 + px] = pts[(b * CF + k) * NPTS + s_nidx[px]];
    }
    __syncthreads();

    int tc = tid & 15, tp = tid >> 4;     /* co = tc*4.., px = tp*8.. */
    float acc[4][8];
#pragma unroll
    for (int i = 0; i < 4; i++)
#pragma unroll
        for (int j = 0; j < 8; j++) acc[i][j] = 0.f;

    for (int k = 0; k < C0; k++) {
        const float4 a  = *(const float4*)(Ws + k * M0 + tc * 4);
        const float4 x0 = *(const float4*)(Xs + k * 128 + tp * 8);
        const float4 x1 = *(const float4*)(Xs + k * 128 + tp * 8 + 4);
        float av[4] = {a.x, a.y, a.z, a.w};
        float xv[8] = {x0.x, x0.y, x0.z, x0.w, x1.x, x1.y, x1.z, x1.w};
#pragma unroll
        for (int i = 0; i < 4; i++)
#pragma unroll
            for (int j = 0; j < 8; j++) acc[i][j] = fmaf(av[i], xv[j], acc[i][j]);
    }

    float ps[4], pq[4];
#pragma unroll
    for (int i = 0; i < 4; i++) {
        int co = tc * 4 + i;
        float s = 0.f, q = 0.f;
#pragma unroll
        for (int j = 0; j < 8; j++) { float v = acc[i][j]; s += v; q += v * v; }
        float* dst = g_y0 + (size_t)co * PXT + px0 + tp * 8;
        *(float4*)dst       = make_float4(acc[i][0], acc[i][1], acc[i][2], acc[i][3]);
        *(float4*)(dst + 4) = make_float4(acc[i][4], acc[i][5], acc[i][6], acc[i][7]);
        ps[i] = s; pq[i] = q;
    }
#pragma unroll
    for (int i = 0; i < 4; i++) {
        ps[i] += __shfl_xor_sync(0xffffffffu, ps[i], 16);
        pq[i] += __shfl_xor_sync(0xffffffffu, pq[i], 16);
    }
    if (!(tid & 16)) {
#pragma unroll
        for (int i = 0; i < 4; i++) {
            atomicAdd(&g_sum[tc * 4 + i], ps[i]);
            atomicAdd(&g_sq[tc * 4 + i], pq[i]);
        }
    }
}

/* -------- layer 1: BN0+ReLU fused load, GEMM(128 x PX x 64) + stats1 -------- */
__global__ __launch_bounds__(256) void k_gemm1(const float* __restrict__ W)
{
    float* Ws  = sm;                 /* 64*128 */
    float* Xs  = sm + 64 * M1;       /* 64*128 */
    float* s_a = sm + 2 * 64 * M1;   /* 64 */
    float* s_c = s_a + 64;

    int tid = threadIdx.x;
    int px0 = blockIdx.x * 128;

    if (tid < 64) { s_a[tid] = g_aa[tid]; s_c[tid] = g_cc[tid]; }
    for (int e = tid; e < M1 * 64; e += 256) {
        int co = e & 127, k = e >> 7;
        Ws[k * M1 + co] = W[co * 64 + k];
    }
    __syncthreads();
    for (int e = tid; e < 64 * 128; e += 256) {
        int k = e >> 7, px = e & 127;
        float v = g_y0[(size_t)k * PXT + px0 + px];
        Xs[k * 128 + px] = fmaxf(fmaf(s_a[k], v, s_c[k]), 0.f);
    }
    __syncthreads();

    int tc = tid & 15, tp = tid >> 4;
    float acc[8][8];
#pragma unroll
    for (int i = 0; i < 8; i++)
#pragma unroll
        for (int j = 0; j < 8; j++) acc[i][j] = 0.f;

    for (int k = 0; k < 64; k++) {
        const float4 a0 = *(const float4*)(Ws + k * M1 + tc * 8);
        const float4 a1 = *(const float4*)(Ws + k * M1 + tc * 8 + 4);
        const float4 b0 = *(const float4*)(Xs + k * 128 + tp * 8);
        const float4 b1 = *(const float4*)(Xs + k * 128 + tp * 8 + 4);
        float av[8] = {a0.x, a0.y, a0.z, a0.w, a1.x, a1.y, a1.z, a1.w};
        float bv[8] = {b0.x, b0.y, b0.z, b0.w, b1.x, b1.y, b1.z, b1.w};
#pragma unroll
        for (int i = 0; i < 8; i++)
#pragma unroll
            for (int j = 0; j < 8; j++) acc[i][j] = fmaf(av[i], bv[j], acc[i][j]);
    }

    float ps[8], pq[8];
#pragma unroll
    for (int i = 0; i < 8; i++) {
        int co = tc * 8 + i;
        float s = 0.f, q = 0.f;
#pragma unroll
        for (int j = 0; j < 8; j++) { float v = acc[i][j]; s += v; q += v * v; }
        float* dst = g_y1 + (size_t)co * PXT + px0 + tp * 8;
        *(float4*)dst       = make_float4(acc[i][0], acc[i][1], acc[i][2], acc[i][3]);
        *(float4*)(dst + 4) = make_float4(acc[i][4], acc[i][5], acc[i][6], acc[i][7]);
        ps[i] = s; pq[i] = q;
    }
#pragma unroll
    for (int i = 0; i < 8; i++) {
        ps[i] += __shfl_xor_sync(0xffffffffu, ps[i], 16);
        pq[i] += __shfl_xor_sync(0xffffffffu, pq[i], 16);
    }
    if (!(tid & 16)) {
#pragma unroll
        for (int i = 0; i < 8; i++) {
            atomicAdd(&g_sum[64 + tc * 8 + i], ps[i]);
            atomicAdd(&g_sq[64 + tc * 8 + i], pq[i]);
        }
    }
}

/* -------- layer 2: BN1+ReLU fused load, GEMM(256 x PX x 128) + stats2
           + max over NS (BN2+ReLU monotone => commute), write raw max -------- */
__global__ __launch_bounds__(256) void k_gemm2(const float* __restrict__ W,
                                               float* __restrict__ out)
{
    float* Ws     = sm;              /* 64*128 (per K-chunk) */
    float* Xs     = sm + 8192;       /* 64*128 */
    float* s_a    = sm + 16384;      /* 128 */
    float* s_c    = s_a + 128;
    float* s_pmax = s_c + 128;       /* 16*128 */

    int tid = threadIdx.x;
    int px0 = blockIdx.x * 128;
    int co0 = blockIdx.y * 128;

    if (tid < 128) { s_a[tid] = g_aa[64 + tid]; s_c[tid] = g_cc[64 + tid]; }

    int tc = tid & 15, tp = tid >> 4;
    float acc[8][8];
#pragma unroll
    for (int i = 0; i < 8; i++)
#pragma unroll
        for (int j = 0; j < 8; j++) acc[i][j] = 0.f;

    for (int kc = 0; kc < 2; kc++) {
        int kb = kc << 6;
        __syncthreads();    /* s_a ready (kc=0) / smem reuse safe (kc=1) */
        for (int e = tid; e < M1 * 64; e += 256) {
            int co = e & 127, k = e >> 7;
            Ws[k * M1 + co] = W[(co0 + co) * M1 + kb + k];
        }
        for (int e = tid; e < 64 * 128; e += 256) {
            int k = e >> 7, px = e & 127;
            float v = g_y1[(size_t)(kb + k) * PXT + px0 + px];
            Xs[k * 128 + px] = fmaxf(fmaf(s_a[kb + k], v, s_c[kb + k]), 0.f);
        }
        __syncthreads();
        for (int k = 0; k < 64; k++) {
            const float4 a0 = *(const float4*)(Ws + k * M1 + tc * 8);
            const float4 a1 = *(const float4*)(Ws + k * M1 + tc * 8 + 4);
            const float4 b0 = *(const float4*)(Xs + k * 128 + tp * 8);
            const float4 b1 = *(const float4*)(Xs + k * 128 + tp * 8 + 4);
            float av[8] = {a0.x, a0.y, a0.z, a0.w, a1.x, a1.y, a1.z, a1.w};
            float bv[8] = {b0.x, b0.y, b0.z, b0.w, b1.x, b1.y, b1.z, b1.w};
#pragma unroll
            for (int i = 0; i < 8; i++)
#pragma unroll
                for (int j = 0; j < 8; j++) acc[i][j] = fmaf(av[i], bv[j], acc[i][j]);
        }
    }

    float ps[8], pq[8], pm[8];
#pragma unroll
    for (int i = 0; i < 8; i++) {
        float s = 0.f, q = 0.f, m = -3.4e38f;
#pragma unroll
        for (int j = 0; j < 8; j++) {
            float v = acc[i][j];
            s += v; q += v * v; m = fmaxf(m, v);
        }
        ps[i] = s; pq[i] = q; pm[i] = m;
    }
#pragma unroll
    for (int i = 0; i < 8; i++) {
        ps[i] += __shfl_xor_sync(0xffffffffu, ps[i], 16);
        pq[i] += __shfl_xor_sync(0xffffffffu, pq[i], 16);
    }
    if (!(tid & 16)) {
#pragma unroll
        for (int i = 0; i < 8; i++) {
            atomicAdd(&g_sum[192 + co0 + tc * 8 + i], ps[i]);
            atomicAdd(&g_sq[192 + co0 + tc * 8 + i], pq[i]);
        }
    }
#pragma unroll
    for (int i = 0; i < 8; i++) s_pmax[tp * 128 + tc * 8 + i] = pm[i];
    __syncthreads();

    /* 4 np-groups x 128 co per tile; each (co,np) lives in exactly one block */
    for (int e = tid; e < 512; e += 256) {
        int g = e >> 7, co = e & 127;
        float v = fmaxf(fmaxf(s_pmax[(4 * g + 0) * 128 + co],
                              s_pmax[(4 * g + 1) * 128 + co]),
                        fmaxf(s_pmax[(4 * g + 2) * 128 + co],
                              s_pmax[(4 * g + 3) * 128 + co]));
        int npf = (px0 >> 5) + g;              /* = b*NPQ + np */
        int b = npf >> 10, np = npf & 1023;
        out[OUT_XYZ + ((b * M2 + co0 + co) * NPQ + np)] = v;
    }
}

/* in-place BN2 + ReLU on the maxed output */
__global__ void k_final(float* __restrict__ out) {
    int i = blockIdx.x * 256 + threadIdx.x;
    if (i < NB * M2 * NPQ) {
        int co = (i >> 10) & 255;
        float v = out[OUT_XYZ + i];
        out[OUT_XYZ + i] = fmaxf(fmaf(g_aa[192 + co], v, g_cc[192 + co]), 0.f);
    }
}

__global__ void k_xyz(const float* __restrict__ xyz, const int* __restrict__ smp,
                      float* __restrict__ out) {
    int i = blockIdx.x * 256 + threadIdx.x;
    if (i < NB * NPQ) {
        int b = i >> 10;
        int si = smp[i];
        const float* s = xyz + (size_t)(b * NPTS + si) * 3;
        out[i * 3 + 0] = s[0];
        out[i * 3 + 1] = s[1];
        out[i * 3 + 2] = s[2];
    }
}

extern "C" void kernel_launch(void* const* d_in, const int* in_sizes, int n_in,
                              void* d_out, int out_size) {
    const float* xyz = (const float*)d_in[0];
    const float* pts = (const float*)d_in[1];
    const int*   smp = (const int*)d_in[2];
    const int*   nbr = (const int*)d_in[3];
    const float* W0  = (const float*)d_in[4];
    const float* g0  = (const float*)d_in[6];
    const float* be0 = (const float*)d_in[7];
    const float* W1  = (const float*)d_in[8];
    const float* g1  = (const float*)d_in[10];
    const float* be1 = (const float*)d_in[11];
    const float* W2  = (const float*)d_in[12];
    const float* g2  = (const float*)d_in[14];
    const float* be2 = (const float*)d_in[15];
    float* out = (float*)d_out;

    const int SM0 = (C0 * M0 + C0 * 128 + 128) * 4;     /* 51968 B */
    const int SM1 = (64 * M1 * 2 + 128) * 4;            /* 66048 B */
    const int SM2 = (64 * M1 * 2 + 256 + 16 * 128) * 4; /* 74752 B */
    cudaFuncSetAttribute(k_gemm0, cudaFuncAttributeMaxDynamicSharedMemorySize, SM0);
    cudaFuncSetAttribute(k_gemm1, cudaFuncAttributeMaxDynamicSharedMemorySize, SM1);
    cudaFuncSetAttribute(k_gemm2, cudaFuncAttributeMaxDynamicSharedMemorySize, SM2);

    k_zero<<<2, 256>>>();
    k_gemm0<<<PXT / 128, 256, SM0>>>(xyz, pts, smp, nbr, W0);
    k_fold<<<1, 64>>>(g0, be0, 0, 64);
    k_gemm1<<<PXT / 128, 256, SM1>>>(W1);
    k_fold<<<1, 128>>>(g1, be1, 64, 128);
    k_gemm2<<<dim3(PXT / 128, 2), 256, SM2>>>(W2, out);
    k_fold<<<1, 256>>>(g2, be2, 192, 256);
    k_final<<<(NB * M2 * NPQ + 255) / 256, 256>>>(out);
    k_xyz<<<(NB * NPQ + 255) / 256, 256>>>(xyz, smp, out);
}

// round 2
// speedup vs baseline: 1.6958x; 1.6958x over previous
#include <cuda_runtime.h>

#define NPTS  4096
#define NPQ   1024
#define NSAMP 32
#define NB    8
#define PXT   262144          /* NB*NPQ*NSAMP */
#define CF    64
#define C0    67
#define M0    64
#define M1    128
#define M2    256
#define EPSB  1e-5f
#define OUT_XYZ 24576         /* NB*NPQ*3 */

/* scratch activations (bss, no runtime alloc) */
__device__ float g_y0[(size_t)M0 * PXT];   /* 64 MB  */
__device__ float g_y1[(size_t)M1 * PXT];   /* 128 MB */

/* pre-transposed weights [k][co] */
__device__ float g_Wt0[C0 * M0];
__device__ float g_Wt1[64 * M1];
__device__ float g_Wt2[M1 * M2];

/* per-channel stats, packed: layer0 @0 (64), layer1 @64 (128), layer2 @192 (256) */
__device__ float g_sum[448];
__device__ float g_sq[448];
__device__ float g_aa[448];
__device__ float g_cc[448];

extern __shared__ float sm[];

/* zero stats + transpose all weights into [k][co] layout (stays hot in L2) */
__global__ void k_prep(const float* __restrict__ W0,
                       const float* __restrict__ W1,
                       const float* __restrict__ W2) {
    int t = blockIdx.x * blockDim.x + threadIdx.x;
    int nth = gridDim.x * blockDim.x;
    if (t < 448) { g_sum[t] = 0.f; g_sq[t] = 0.f; }
    for (int e = t; e < C0 * M0; e += nth) {
        int k = e / M0, co = e % M0;
        g_Wt0[e] = W0[co * C0 + k];
    }
    for (int e = t; e < 64 * M1; e += nth) {
        int k = e >> 7, co = e & 127;
        g_Wt1[e] = W1[co * 64 + k];
    }
    for (int e = t; e < M1 * M2; e += nth) {
        int k = e >> 8, co = e & 255;
        g_Wt2[e] = W2[co * M1 + k];
    }
}

__global__ void k_fold(const float* __restrict__ gamma,
                       const float* __restrict__ beta, int off, int C) {
    int i = blockIdx.x * blockDim.x + threadIdx.x;
    if (i < C) {
        const float inv = 1.0f / (float)PXT;
        float mu  = g_sum[off + i] * inv;
        float var = g_sq[off + i] * inv - mu * mu;
        float r   = rsqrtf(var + EPSB);
        float a   = gamma[i] * r;
        g_aa[off + i] = a;
        g_cc[off + i] = beta[i] - a * mu;
    }
}

/* -------- layer 0: gather + GEMM(64 x PX x 67) + stats0 -------- */
__global__ __launch_bounds__(256) void k_gemm0(
    const float* __restrict__ xyz, const float* __restrict__ pts,
    const int* __restrict__ smp, const int* __restrict__ nbr)
{
    float* Ws = sm;                       /* [k][co]  C0*M0  */
    float* Xs = sm + C0 * M0;             /* [k][px]  C0*128 */
    int*   s_nidx = (int*)(sm + C0 * M0 + C0 * 128);

    int tid = threadIdx.x;
    int px0 = blockIdx.x * 128;
    int b   = px0 >> 15;                  /* 128-px tile never crosses a batch */

    /* straight copy, coalesced + conflict-free (already [k][co]) */
    for (int e = tid; e < (C0 * M0) / 4; e += 256)
        ((float4*)Ws)[e] = ((const float4*)g_Wt0)[e];

    if (tid < 128) {
        int pxg = px0 + tid;
        int ni  = nbr[pxg];
        s_nidx[tid] = ni;
        int si  = smp[pxg >> 5];
        const float* xn = xyz + (size_t)(b * NPTS + ni) * 3;
        const float* xc = xyz + (size_t)(b * NPTS + si) * 3;
        Xs[0 * 128 + tid] = xn[0] - xc[0];
        Xs[1 * 128 + tid] = xn[1] - xc[1];
        Xs[2 * 128 + tid] = xn[2] - xc[2];
    }
    __syncthreads();
    for (int e = tid; e < CF * 128; e += 256) {
        int k = e >> 7, px = e & 127;
        Xs[(3 + k) * 128 + px] = pts[(b * CF + k) * NPTS + s_nidx[px]];
    }
    __syncthreads();

    int tc = tid & 15, tp = tid >> 4;     /* co = tc*4.., px = tp*8.. */
    float acc[4][8];
#pragma unroll
    for (int i = 0; i < 4; i++)
#pragma unroll
        for (int j = 0; j < 8; j++) acc[i][j] = 0.f;

#pragma unroll 2
    for (int k = 0; k < C0; k++) {
        const float4 a  = *(const float4*)(Ws + k * M0 + tc * 4);
        const float4 x0 = *(const float4*)(Xs + k * 128 + tp * 8);
        const float4 x1 = *(const float4*)(Xs + k * 128 + tp * 8 + 4);
        float av[4] = {a.x, a.y, a.z, a.w};
        float xv[8] = {x0.x, x0.y, x0.z, x0.w, x1.x, x1.y, x1.z, x1.w};
#pragma unroll
        for (int i = 0; i < 4; i++)
#pragma unroll
            for (int j = 0; j < 8; j++) acc[i][j] = fmaf(av[i], xv[j], acc[i][j]);
    }

    float ps[4], pq[4];
#pragma unroll
    for (int i = 0; i < 4; i++) {
        int co = tc * 4 + i;
        float s = 0.f, q = 0.f;
#pragma unroll
        for (int j = 0; j < 8; j++) { float v = acc[i][j]; s += v; q += v * v; }
        float* dst = g_y0 + (size_t)co * PXT + px0 + tp * 8;
        *(float4*)dst       = make_float4(acc[i][0], acc[i][1], acc[i][2], acc[i][3]);
        *(float4*)(dst + 4) = make_float4(acc[i][4], acc[i][5], acc[i][6], acc[i][7]);
        ps[i] = s; pq[i] = q;
    }
#pragma unroll
    for (int i = 0; i < 4; i++) {
        ps[i] += __shfl_xor_sync(0xffffffffu, ps[i], 16);
        pq[i] += __shfl_xor_sync(0xffffffffu, pq[i], 16);
    }
    if (!(tid & 16)) {
#pragma unroll
        for (int i = 0; i < 4; i++) {
            atomicAdd(&g_sum[tc * 4 + i], ps[i]);
            atomicAdd(&g_sq[tc * 4 + i], pq[i]);
        }
    }
}

/* -------- layer 1: BN0+ReLU fused load, GEMM(128 x PX x 64) + stats1
   split register tiles: co in {tc*4..+3, 64+tc*4..+3}, px in {tp*4..+3, 64+tp*4..+3}
   -> all LDS.128 conflict-free -------- */
__global__ __launch_bounds__(256) void k_gemm1()
{
    float* Ws  = sm;                 /* [k][co] 64*128 */
    float* Xs  = sm + 64 * M1;       /* [k][px] 64*128 */
    float* s_a = sm + 2 * 64 * M1;   /* 64 */
    float* s_c = s_a + 64;

    int tid = threadIdx.x;
    int px0 = blockIdx.x * 128;

    if (tid < 64) { s_a[tid] = g_aa[tid]; s_c[tid] = g_cc[tid]; }
    for (int e = tid; e < (64 * M1) / 4; e += 256)
        ((float4*)Ws)[e] = ((const float4*)g_Wt1)[e];
    __syncthreads();
    for (int e = tid; e < 64 * 128; e += 256) {
        int k = e >> 7, px = e & 127;
        float v = g_y0[(size_t)k * PXT + px0 + px];
        Xs[k * 128 + px] = fmaxf(fmaf(s_a[k], v, s_c[k]), 0.f);
    }
    __syncthreads();

    int tc = tid & 15, tp = tid >> 4;
    float acc[8][8];
#pragma unroll
    for (int i = 0; i < 8; i++)
#pragma unroll
        for (int j = 0; j < 8; j++) acc[i][j] = 0.f;

#pragma unroll 2
    for (int k = 0; k < 64; k++) {
        const float4 a0 = *(const float4*)(Ws + k * M1 + tc * 4);
        const float4 a1 = *(const float4*)(Ws + k * M1 + 64 + tc * 4);
        const float4 b0 = *(const float4*)(Xs + k * 128 + tp * 4);
        const float4 b1 = *(const float4*)(Xs + k * 128 + 64 + tp * 4);
        float av[8] = {a0.x, a0.y, a0.z, a0.w, a1.x, a1.y, a1.z, a1.w};
        float bv[8] = {b0.x, b0.y, b0.z, b0.w, b1.x, b1.y, b1.z, b1.w};
#pragma unroll
        for (int i = 0; i < 8; i++)
#pragma unroll
            for (int j = 0; j < 8; j++) acc[i][j] = fmaf(av[i], bv[j], acc[i][j]);
    }

    float ps[8], pq[8];
#pragma unroll
    for (int i = 0; i < 8; i++) {
        int co = (i < 4) ? (tc * 4 + i) : (64 + tc * 4 + i - 4);
        float s = 0.f, q = 0.f;
#pragma unroll
        for (int j = 0; j < 8; j++) { float v = acc[i][j]; s += v; q += v * v; }
        float* dst = g_y1 + (size_t)co * PXT + px0;
        *(float4*)(dst + tp * 4)      = make_float4(acc[i][0], acc[i][1], acc[i][2], acc[i][3]);
        *(float4*)(dst + 64 + tp * 4) = make_float4(acc[i][4], acc[i][5], acc[i][6], acc[i][7]);
        ps[i] = s; pq[i] = q;
    }
#pragma unroll
    for (int i = 0; i < 8; i++) {
        ps[i] += __shfl_xor_sync(0xffffffffu, ps[i], 16);
        pq[i] += __shfl_xor_sync(0xffffffffu, pq[i], 16);
    }
    if (!(tid & 16)) {
#pragma unroll
        for (int i = 0; i < 8; i++) {
            int co = (i < 4) ? (tc * 4 + i) : (64 + tc * 4 + i - 4);
            atomicAdd(&g_sum[64 + co], ps[i]);
            atomicAdd(&g_sq[64 + co], pq[i]);
        }
    }
}

/* -------- layer 2: BN1+ReLU fused load, GEMM(256 x PX x 128) + stats2
           + max over NS (BN2+ReLU monotone => commute), write raw max -------- */
__global__ __launch_bounds__(256) void k_gemm2(float* __restrict__ out)
{
    float* Ws     = sm;              /* [k][co_local] 64*128 per K-chunk */
    float* Xs     = sm + 8192;       /* [k][px] 64*128 */
    float* s_a    = sm + 16384;      /* 128 */
    float* s_c    = s_a + 128;
    float* s_pmax = s_c + 128;       /* 32 rows x 128 co, row r = px r*4..r*4+3 */

    int tid = threadIdx.x;
    int px0 = blockIdx.x * 128;
    int co0 = blockIdx.y * 128;

    if (tid < 128) { s_a[tid] = g_aa[64 + tid]; s_c[tid] = g_cc[64 + tid]; }

    int tc = tid & 15, tp = tid >> 4;
    float acc[8][8];
#pragma unroll
    for (int i = 0; i < 8; i++)
#pragma unroll
        for (int j = 0; j < 8; j++) acc[i][j] = 0.f;

    for (int kc = 0; kc < 2; kc++) {
        int kb = kc << 6;
        __syncthreads();    /* s_a ready (kc=0) / smem reuse safe (kc=1) */
        /* Wt2 is [k 0..127][co 0..255]; copy rows kb..kb+63, cols co0..co0+127 */
        for (int e = tid; e < 2048; e += 256) {
            int k = e >> 5, cq = e & 31;
            ((float4*)Ws)[k * 32 + cq] =
                ((const float4*)g_Wt2)[(size_t)(kb + k) * 64 + (co0 >> 2) + cq];
        }
        for (int e = tid; e < 64 * 128; e += 256) {
            int k = e >> 7, px = e & 127;
            float v = g_y1[(size_t)(kb + k) * PXT + px0 + px];
            Xs[k * 128 + px] = fmaxf(fmaf(s_a[kb + k], v, s_c[kb + k]), 0.f);
        }
        __syncthreads();
#pragma unroll 2
        for (int k = 0; k < 64; k++) {
            const float4 a0 = *(const float4*)(Ws + k * M1 + tc * 4);
            const float4 a1 = *(const float4*)(Ws + k * M1 + 64 + tc * 4);
            const float4 b0 = *(const float4*)(Xs + k * 128 + tp * 4);
            const float4 b1 = *(const float4*)(Xs + k * 128 + 64 + tp * 4);
            float av[8] = {a0.x, a0.y, a0.z, a0.w, a1.x, a1.y, a1.z, a1.w};
            float bv[8] = {b0.x, b0.y, b0.z, b0.w, b1.x, b1.y, b1.z, b1.w};
#pragma unroll
            for (int i = 0; i < 8; i++)
#pragma unroll
                for (int j = 0; j < 8; j++) acc[i][j] = fmaf(av[i], bv[j], acc[i][j]);
        }
    }

    float ps[8], pq[8], pml[8], pmh[8];
#pragma unroll
    for (int i = 0; i < 8; i++) {
        float s = 0.f, q = 0.f, ml = -3.4e38f, mh = -3.4e38f;
#pragma unroll
        for (int j = 0; j < 4; j++) {
            float v = acc[i][j];
            s += v; q += v * v; ml = fmaxf(ml, v);
        }
#pragma unroll
        for (int j = 4; j < 8; j++) {
            float v = acc[i][j];
            s += v; q += v * v; mh = fmaxf(mh, v);
        }
        ps[i] = s; pq[i] = q; pml[i] = ml; pmh[i] = mh;
    }
#pragma unroll
    for (int i = 0; i < 8; i++) {
        ps[i] += __shfl_xor_sync(0xffffffffu, ps[i], 16);
        pq[i] += __shfl_xor_sync(0xffffffffu, pq[i], 16);
    }
    if (!(tid & 16)) {
#pragma unroll
        for (int i = 0; i < 8; i++) {
            int co = (i < 4) ? (tc * 4 + i) : (64 + tc * 4 + i - 4);
            atomicAdd(&g_sum[192 + co0 + co], ps[i]);
            atomicAdd(&g_sq[192 + co0 + co], pq[i]);
        }
    }
#pragma unroll
    for (int i = 0; i < 8; i++) {
        int co = (i < 4) ? (tc * 4 + i) : (64 + tc * 4 + i - 4);
        s_pmax[tp * 128 + co]        = pml[i];   /* px tp*4..+3      -> row tp    */
        s_pmax[(16 + tp) * 128 + co] = pmh[i];   /* px 64+tp*4..+3   -> row 16+tp */
    }
    __syncthreads();

    /* 4 np-groups (32 px each = rows 8g..8g+7) x 128 co per tile */
    for (int e = tid; e < 512; e += 256) {
        int g = e >> 7, co = e & 127;
        float v = -3.4e38f;
#pragma unroll
        for (int r = 0; r < 8; r++)
            v = fmaxf(v, s_pmax[(8 * g + r) * 128 + co]);
        int npf = (px0 >> 5) + g;              /* = b*NPQ + np */
        int b = npf >> 10, np = npf & 1023;
        out[OUT_XYZ + ((b * M2 + co0 + co) * NPQ + np)] = v;
    }
}

/* in-place BN2 + ReLU on the maxed output */
__global__ void k_final(float* __restrict__ out) {
    int i = blockIdx.x * 256 + threadIdx.x;
    if (i < NB * M2 * NPQ) {
        int co = (i >> 10) & 255;
        float v = out[OUT_XYZ + i];
        out[OUT_XYZ + i] = fmaxf(fmaf(g_aa[192 + co], v, g_cc[192 + co]), 0.f);
    }
}

__global__ void k_xyz(const float* __restrict__ xyz, const int* __restrict__ smp,
                      float* __restrict__ out) {
    int i = blockIdx.x * 256 + threadIdx.x;
    if (i < NB * NPQ) {
        int b = i >> 10;
        int si = smp[i];
        const float* s = xyz + (size_t)(b * NPTS + si) * 3;
        out[i * 3 + 0] = s[0];
        out[i * 3 + 1] = s[1];
        out[i * 3 + 2] = s[2];
    }
}

extern "C" void kernel_launch(void* const* d_in, const int* in_sizes, int n_in,
                              void* d_out, int out_size) {
    const float* xyz = (const float*)d_in[0];
    const float* pts = (const float*)d_in[1];
    const int*   smp = (const int*)d_in[2];
    const int*   nbr = (const int*)d_in[3];
    const float* W0  = (const float*)d_in[4];
    const float* g0  = (const float*)d_in[6];
    const float* be0 = (const float*)d_in[7];
    const float* W1  = (const float*)d_in[8];
    const float* g1  = (const float*)d_in[10];
    const float* be1 = (const float*)d_in[11];
    const float* W2  = (const float*)d_in[12];
    const float* g2  = (const float*)d_in[14];
    const float* be2 = (const float*)d_in[15];
    float* out = (float*)d_out;

    const int SM0 = (C0 * M0 + C0 * 128 + 128) * 4;       /* 51968 B */
    const int SM1 = (64 * M1 * 2 + 128) * 4;              /* 66048 B */
    const int SM2 = (64 * M1 * 2 + 256 + 32 * 128) * 4;   /* 82944 B */
    cudaFuncSetAttribute(k_gemm0, cudaFuncAttributeMaxDynamicSharedMemorySize, SM0);
    cudaFuncSetAttribute(k_gemm1, cudaFuncAttributeMaxDynamicSharedMemorySize, SM1);
    cudaFuncSetAttribute(k_gemm2, cudaFuncAttributeMaxDynamicSharedMemorySize, SM2);

    k_prep<<<64, 256>>>(W0, W1, W2);
    k_gemm0<<<PXT / 128, 256, SM0>>>(xyz, pts, smp, nbr);
    k_fold<<<1, 64>>>(g0, be0, 0, 64);
    k_gemm1<<<PXT / 128, 256, SM1>>>();
    k_fold<<<1, 128>>>(g1, be1, 64, 128);
    k_gemm2<<<dim3(PXT / 128, 2), 256, SM2>>>(out);
    k_fold<<<1, 256>>>(g2, be2, 192, 256);
    k_final<<<(NB * M2 * NPQ + 255) / 256, 256>>>(out);
    k_xyz<<<(NB * NPQ + 255) / 256, 256>>>(xyz, smp, out);
}